// round 12
// baseline (speedup 1.0000x reference)
#include <cuda_runtime.h>
#include <cuda_bf16.h>
#include <math_constants.h>
#include <cstdint>

// Problem constants
#define NPOS 65536
#define DIM  64
#define KCB  512
#define NCHW_ELEMS 4194304
#define GRID 512
#define NT   256
#define WND  2e-5f          // tie window: > 2x (split err ~1e-6 + mma accum err)

// smem layout (bytes)
#define A_STRIDE 272        // A row: 136 bf16 (128 used) -> banks 4*row+q unique
#define B_STRIDE 528        // B row: 264 bf16 (256 used) -> conflict-free
#define OFF_A    0          // A: 128 rows x 272B = 34816
#define OFF_B    34816      // B chunk: 64 rows x 528B = 33792 (reused as qs[128][65])
#define OFF_XS   68608      // Xs fp32 [64][128] = 32768
#define OFF_NES  101376     // ne[512] = 2048
#define OFF_XN   103424     // xn[128] = 512
#define OFF_WIDX 103936     // widx[128] = 512
#define OFF_RED  104448     // red[256] = 1024
#define SMEM_TOTAL 105472

// Scratch (allocation-free __device__ globals)
__device__ int   g_hist[KCB];
__device__ float g_ne[KCB];
__device__ float g_partial[GRID];
// B_cat = [e0 | e1 | e1 | e0] per code (K=256 bf16)
__device__ __align__(16) __nv_bfloat16 g_ebcat[KCB * 256];

__device__ __forceinline__ void mma16816(float* c, const uint32_t* a,
                                         uint32_t b0, uint32_t b1) {
    asm volatile(
        "mma.sync.aligned.m16n8k16.row.col.f32.bf16.bf16.f32 "
        "{%0,%1,%2,%3}, {%4,%5,%6,%7}, {%8,%9}, {%0,%1,%2,%3};"
        : "+f"(c[0]), "+f"(c[1]), "+f"(c[2]), "+f"(c[3])
        : "r"(a[0]), "r"(a[1]), "r"(a[2]), "r"(a[3]), "r"(b0), "r"(b1));
}
__device__ __forceinline__ uint32_t pack_bf16(__nv_bfloat16 lo, __nv_bfloat16 hi) {
    return (uint32_t)__bfloat16_as_ushort(lo) | ((uint32_t)__bfloat16_as_ushort(hi) << 16);
}

// ---------------------------------------------------------------------------
// Init: zero hist, ||e||^2 (exact chain — unchanged bits), bf16 e-split concat.
// ---------------------------------------------------------------------------
__global__ void vq_init_kernel(const float* __restrict__ emb) {
    int k = blockIdx.x * 128 + threadIdx.x;   // 0..511
    g_hist[k] = 0;
    const float4* e4 = (const float4*)(emb + k * DIM);
    float s = 0.f;
#pragma unroll
    for (int j = 0; j < 16; ++j) {
        float4 v = e4[j];
        s = fmaf(v.x, v.x, s);
        s = fmaf(v.y, v.y, s);
        s = fmaf(v.z, v.z, s);
        s = fmaf(v.w, v.w, s);
    }
    g_ne[k] = s;
    __nv_bfloat16* row = &g_ebcat[k * 256];
#pragma unroll
    for (int d = 0; d < DIM; ++d) {
        float v = emb[k * DIM + d];
        __nv_bfloat16 e0 = __float2bfloat16_rn(v);
        float r1 = v - __bfloat162float(e0);
        __nv_bfloat16 e1 = __float2bfloat16_rn(r1);
        row[d]       = e0;   // ks 0-3  pairs A x0
        row[64 + d]  = e1;   // ks 4-7  pairs A x1
        row[128 + d] = e1;   // ks 8-11 pairs A x0
        row[192 + d] = e0;   // ks 12-15 pairs A x1
    }
}

// Exact dist — bit-identical to R9 semantics: single fp32 fmaf accumulator,
// d ascending, then rn-emulated jax rounding.
__device__ __forceinline__ float exact_dist(const float* __restrict__ emb,
                                            const float* Xs, int p, int k,
                                            float nx, float ne) {
    const float4* er = (const float4*)(emb + k * DIM);
    float s = 0.f;
#pragma unroll
    for (int i = 0; i < 16; ++i) {
        float4 e4 = er[i];
        s = fmaf(Xs[(4 * i + 0) * 128 + p], e4.x, s);
        s = fmaf(Xs[(4 * i + 1) * 128 + p], e4.y, s);
        s = fmaf(Xs[(4 * i + 2) * 128 + p], e4.z, s);
        s = fmaf(Xs[(4 * i + 3) * 128 + p], e4.w, s);
    }
    return __fsub_rn(__fadd_rn(nx, ne), __fmul_rn(2.0f, s));
}

// ---------------------------------------------------------------------------
// Fused kernel: HMMA bf16x4-split distance GEMM + conservative-exact argmin
// + gather + straight-through + both output layouts + loss partial.
// Grid 512 x 256 threads. Block = 128 positions x 512 codes (8 chunks of 64).
// Warp w: rows w*16 + gr, + gr+8 (gr = lane/4). Cols: chunk*64 + nt*8 + 2q+{0,1}.
// ---------------------------------------------------------------------------
__global__ __launch_bounds__(NT) void vq_fused_kernel(
    const float* __restrict__ x, const float* __restrict__ emb,
    float* __restrict__ out)
{
    extern __shared__ char smem[];
    float* Xs   = (float*)(smem + OFF_XS);
    float* nes  = (float*)(smem + OFF_NES);
    float* xn   = (float*)(smem + OFF_XN);
    int*   widx = (int*)(smem + OFF_WIDX);
    float* red  = (float*)(smem + OFF_RED);

    const int tid = threadIdx.x;
    const int posBase = blockIdx.x * 128;
    const int b  = posBase >> 10;
    const int hw = posBase & 1023;
    const float* xb = x + (size_t)b * 65536 + hw;

    // Load X fp32 tile [d][p]
#pragma unroll
    for (int it = 0; it < 8; ++it) {
        int j = it * 1024 + tid * 4;
        int d = j >> 7, p = j & 127;
        *(float4*)&Xs[d * 128 + p] = *(const float4*)&xb[d * 1024 + p];
    }
    nes[tid] = g_ne[tid];
    nes[tid + 256] = g_ne[tid + 256];
    __syncthreads();

    // A fill: bf16 2-split, A[p][k] = [x0(0..63) | x1(64..127)], pad-272B rows
    {
        int p = tid >> 1;
        int dbase = (tid & 1) * 32;
        char* arow = smem + OFF_A + p * A_STRIDE;
#pragma unroll
        for (int j = 0; j < 16; ++j) {
            int d = dbase + 2 * j;
            float va = Xs[d * 128 + p];
            float vb = Xs[(d + 1) * 128 + p];
            __nv_bfloat16 a0 = __float2bfloat16_rn(va);
            __nv_bfloat16 a1 = __float2bfloat16_rn(va - __bfloat162float(a0));
            __nv_bfloat16 c0 = __float2bfloat16_rn(vb);
            __nv_bfloat16 c1 = __float2bfloat16_rn(vb - __bfloat162float(c0));
            *(uint32_t*)(arow + d * 2)       = pack_bf16(a0, c0);   // x0
            *(uint32_t*)(arow + 128 + d * 2) = pack_bf16(a1, c1);   // x1
        }
    }
    // nx per position (R9-equivalent chains: 4x16 fma, ((s0+s1)+s2)+s3)
    if (tid < 128) {
        float sg[4];
#pragma unroll
        for (int g = 0; g < 4; ++g) {
            float s = 0.f;
#pragma unroll
            for (int j = 0; j < 16; ++j) {
                float v = Xs[(g * 16 + j) * 128 + tid];
                s = fmaf(v, v, s);
            }
            sg[g] = s;
        }
        xn[tid] = ((sg[0] + sg[1]) + sg[2]) + sg[3];
    }
    __syncthreads();

    // Preload A fragments: 8 ksteps x 4 regs (m16n8k16 A layout)
    const int w = tid >> 5, lane = tid & 31, gr = lane >> 2, q = lane & 3;
    const int m0 = w * 16 + gr, m1 = m0 + 8;
    uint32_t afr[8][4];
    {
        const char* a0p = smem + OFF_A + m0 * A_STRIDE + q * 4;
        const char* a1p = a0p + 8 * A_STRIDE;
#pragma unroll
        for (int ks = 0; ks < 8; ++ks) {
            afr[ks][0] = *(const uint32_t*)(a0p + ks * 32);
            afr[ks][1] = *(const uint32_t*)(a1p + ks * 32);
            afr[ks][2] = *(const uint32_t*)(a0p + ks * 32 + 16);
            afr[ks][3] = *(const uint32_t*)(a1p + ks * 32 + 16);
        }
    }
    const float nx0 = xn[m0], nx1 = xn[m1];

    float runmin0 = CUDART_INF_F, runmin1 = CUDART_INF_F;
    float bestd0 = CUDART_INF_F, bestd1 = CUDART_INF_F;
    int   bestk0 = 0, bestk1 = 0;

    for (int ch = 0; ch < 8; ++ch) {
        __syncthreads();   // B buffer reuse
        // Load B chunk: 64 codes x 256 bf16 -> pad-528B rows
        {
            const uint4* src = (const uint4*)g_ebcat + ch * 2048;
#pragma unroll
            for (int it = 0; it < 8; ++it) {
                int j = it * 256 + tid;
                int r = j >> 5, u = j & 31;
                *(uint4*)(smem + OFF_B + r * B_STRIDE + u * 16) = src[j];
            }
        }
        __syncthreads();

        float acc[8][4];
#pragma unroll
        for (int nt = 0; nt < 8; ++nt) {
            acc[nt][0] = 0.f; acc[nt][1] = 0.f; acc[nt][2] = 0.f; acc[nt][3] = 0.f;
        }

        const char* bbase = smem + OFF_B + gr * B_STRIDE + q * 4;
#pragma unroll
        for (int ks = 0; ks < 16; ++ks) {
            const uint32_t* a = afr[ks & 7];
#pragma unroll
            for (int nt = 0; nt < 8; ++nt) {
                uint32_t b0 = *(const uint32_t*)(bbase + nt * 8 * B_STRIDE + ks * 32);
                uint32_t b1 = *(const uint32_t*)(bbase + nt * 8 * B_STRIDE + ks * 32 + 16);
                mma16816(acc[nt], a, b0, b1);
            }
        }

        // Epilogue pass 1: convert to dist in place, update running tensor-min
#pragma unroll
        for (int nt = 0; nt < 8; ++nt) {
            int k0 = ch * 64 + nt * 8 + 2 * q;
            float2 ne2 = *(float2*)&nes[k0];
            float d00 = __fsub_rn(__fadd_rn(nx0, ne2.x), __fmul_rn(2.0f, acc[nt][0]));
            float d01 = __fsub_rn(__fadd_rn(nx0, ne2.y), __fmul_rn(2.0f, acc[nt][1]));
            float d10 = __fsub_rn(__fadd_rn(nx1, ne2.x), __fmul_rn(2.0f, acc[nt][2]));
            float d11 = __fsub_rn(__fadd_rn(nx1, ne2.y), __fmul_rn(2.0f, acc[nt][3]));
            acc[nt][0] = d00; acc[nt][1] = d01; acc[nt][2] = d10; acc[nt][3] = d11;
            runmin0 = fminf(runmin0, fminf(d00, d01));
            runmin1 = fminf(runmin1, fminf(d10, d11));
        }
        // Pass 2: exact recompute for candidates within window of running min.
        // runmin >= final global min, so every final-window candidate triggers.
        const float thr0 = runmin0 + WND, thr1 = runmin1 + WND;
#pragma unroll
        for (int nt = 0; nt < 8; ++nt) {
            int k0 = ch * 64 + nt * 8 + 2 * q;
            if (acc[nt][0] < thr0) {
                float ex = exact_dist(emb, Xs, m0, k0, nx0, nes[k0]);
                if (ex < bestd0) { bestd0 = ex; bestk0 = k0; }
            }
            if (acc[nt][1] < thr0) {
                float ex = exact_dist(emb, Xs, m0, k0 + 1, nx0, nes[k0 + 1]);
                if (ex < bestd0) { bestd0 = ex; bestk0 = k0 + 1; }
            }
            if (acc[nt][2] < thr1) {
                float ex = exact_dist(emb, Xs, m1, k0, nx1, nes[k0]);
                if (ex < bestd1) { bestd1 = ex; bestk1 = k0; }
            }
            if (acc[nt][3] < thr1) {
                float ex = exact_dist(emb, Xs, m1, k0 + 1, nx1, nes[k0 + 1]);
                if (ex < bestd1) { bestd1 = ex; bestk1 = k0 + 1; }
            }
        }
    }

    // Reduce exact argmin across the 4 lanes sharing each row (tie: smaller k)
#pragma unroll
    for (int off = 1; off <= 2; off <<= 1) {
        float ov0 = __shfl_xor_sync(0xffffffffu, bestd0, off);
        int   oi0 = __shfl_xor_sync(0xffffffffu, bestk0, off);
        if (ov0 < bestd0 || (ov0 == bestd0 && oi0 < bestk0)) { bestd0 = ov0; bestk0 = oi0; }
        float ov1 = __shfl_xor_sync(0xffffffffu, bestd1, off);
        int   oi1 = __shfl_xor_sync(0xffffffffu, bestk1, off);
        if (ov1 < bestd1 || (ov1 == bestd1 && oi1 < bestk1)) { bestd1 = ov1; bestk1 = oi1; }
    }
    if (q == 0) {
        widx[m0] = bestk0;
        widx[m1] = bestk1;
        atomicAdd(&g_hist[bestk0], 1);
        atomicAdd(&g_hist[bestk1], 1);
    }
    __syncthreads();

    // ---- Outputs (qs reuses B chunk region) ----
    float* qs = (float*)(smem + OFF_B);   // [128][65]
    float* out_nchw = out + 1;
    float* out_flat = out + 2 + NCHW_ELEMS;

#pragma unroll
    for (int it = 0; it < 32; ++it) {
        int j = it * 256 + tid;
        int p = j >> 6, d = j & 63;
        qs[p * 65 + d] = emb[widx[p] * DIM + d];
    }
    __syncthreads();

    float lsum = 0.f;
#pragma unroll
    for (int it = 0; it < 32; ++it) {
        int j = it * 256 + tid;
        int d = j >> 7, p = j & 127;
        size_t g = (size_t)b * 65536 + (size_t)d * 1024 + hw + p;
        float qv = qs[p * 65 + d];
        float xv = Xs[d * 128 + p];
        float df  = __fsub_rn(qv, xv);      // fl32(q - x)
        float qst = __fadd_rn(xv, df);      // fl32(x + (q - x))
        out_nchw[g] = qst;
        qs[p * 65 + d] = qst;
        lsum = fmaf(df, df, lsum);
    }
    __syncthreads();

#pragma unroll
    for (int it = 0; it < 32; ++it) {
        int j = it * 256 + tid;
        int p = j >> 6, d = j & 63;
        out_flat[(size_t)(posBase + p) * DIM + d] = qs[p * 65 + d];
    }

    red[tid] = lsum;
    __syncthreads();
    for (int s = 128; s > 0; s >>= 1) {
        if (tid < s) red[tid] += red[tid + s];
        __syncthreads();
    }
    if (tid == 0) g_partial[blockIdx.x] = red[0];
}

// ---------------------------------------------------------------------------
// Finalize: loss scalar + perplexity (fp32, deterministic).
// ---------------------------------------------------------------------------
__global__ void vq_finalize_kernel(float* __restrict__ out) {
    __shared__ float red[512];
    const int t = threadIdx.x;

    red[t] = g_partial[t];
    __syncthreads();
    for (int s = 256; s > 0; s >>= 1) {
        if (t < s) red[t] += red[t + s];
        __syncthreads();
    }
    if (t == 0) out[0] = 1.25f * (red[0] / (float)NCHW_ELEMS);
    __syncthreads();

    float p = (float)g_hist[t] * (1.0f / 65536.0f);
    red[t] = p * logf(p + 1e-10f);
    __syncthreads();
    for (int s = 256; s > 0; s >>= 1) {
        if (t < s) red[t] += red[t + s];
        __syncthreads();
    }
    if (t == 0) out[NCHW_ELEMS + 1] = expf(-red[0]);
}

// ---------------------------------------------------------------------------
extern "C" void kernel_launch(void* const* d_in, const int* in_sizes, int n_in,
                              void* d_out, int out_size) {
    const float* x   = (const float*)d_in[0];
    const float* emb = (const float*)d_in[1];
    float* out = (float*)d_out;

    cudaFuncSetAttribute(vq_fused_kernel,
                         cudaFuncAttributeMaxDynamicSharedMemorySize, SMEM_TOTAL);

    vq_init_kernel<<<4, 128>>>(emb);
    vq_fused_kernel<<<GRID, NT, SMEM_TOTAL>>>(x, emb, out);
    vq_finalize_kernel<<<1, 512>>>(out);
}

// round 13
// speedup vs baseline: 3.6953x; 3.6953x over previous
#include <cuda_runtime.h>
#include <math_constants.h>

// Problem constants
#define NPOS 65536   // 64 * 32 * 32 positions
#define DIM  64      // embedding dim
#define KCB  512     // codebook size
#define NCHW_ELEMS 4194304  // 64*64*32*32
#define GRID 1024

typedef unsigned long long ull;

// Scratch (allocation-free: __device__ globals)
// g_hist[0..511] = histogram, g_hist[512] = completion counter (memset each replay)
__device__ int   g_hist[KCB + 1];
__device__ float g_partial[GRID];

// Packed fp32x2 FMA (Blackwell): per-lane IEEE identical to scalar fmaf.
__device__ __forceinline__ void ffma2(ull& acc, ull a, ull b) {
    asm("fma.rn.f32x2 %0, %1, %2, %0;" : "+l"(acc) : "l"(a), "l"(b));
}
__device__ __forceinline__ ull dup2(float v) {
    ull r;
    asm("mov.b64 %0, {%1, %1};" : "=l"(r) : "f"(v));
    return r;
}
__device__ __forceinline__ void unpack2(ull p, float& lo, float& hi) {
    asm("mov.b64 {%0, %1}, %2;" : "=f"(lo), "=f"(hi) : "l"(p));
}

// ||e_k||^2 — exact chain (bitwise identical to the former init kernel)
__device__ __forceinline__ float code_norm(const float* __restrict__ emb, int k) {
    const float4* e4 = (const float4*)(emb + k * DIM);
    float s = 0.f;
#pragma unroll
    for (int j = 0; j < 16; ++j) {
        float4 v = e4[j];
        s = fmaf(v.x, v.x, s);
        s = fmaf(v.y, v.y, s);
        s = fmaf(v.z, v.z, s);
        s = fmaf(v.w, v.w, s);
    }
    return s;
}

// ---------------------------------------------------------------------------
// Single fused kernel (R9 GEMM core verbatim): FFMA2 argmin GEMM + fused
// outputs + loss partial + last-block finalize.
// dist = fl32(fl32(nx+ne) - fl32(2*s)), first-index argmin (jax emulation).
// Grid: 1024 blocks x 256 threads. Block = 64 positions x 512 codes,
// 4 chunks of 128 codes. Warp ry: positions ry*8..ry*8+7 (f32x2 pairs).
// Lane cx: codes ch*128 + cx + {0,32,64,96}.
// ---------------------------------------------------------------------------
__global__ __launch_bounds__(256, 2) void vq_fused_kernel(
    const float* __restrict__ x, const float* __restrict__ emb,
    float* __restrict__ out)
{
    __shared__ float Xs[64 * 64];      // [d][pos], d-major (pos pairs adjacent)
    __shared__ float Es[128 * 65];     // [code][d] pad 65; reused as qs[64][65]
    __shared__ float nes[KCB];         // ||e_k||^2 (computed in-block, L2-hot)
    __shared__ float xpart[4 * 64];    // nx partials; reused as reduction buf
    __shared__ float xn[64];           // ||x_p||^2 (binade-correct suffices)
    __shared__ int   widx[64];         // winning code per position
    __shared__ int   isLast;

    const int tid = threadIdx.x;
    const int posBase = blockIdx.x * 64;
    const int b  = posBase >> 10;       // 1024 positions per batch image
    const int hw = posBase & 1023;
    const float* xb = x + (size_t)b * 65536 + hw;  // + d*1024 + p

    // Load X tile (float4, coalesced): Xs[d*64+p]
#pragma unroll
    for (int it = 0; it < 4; ++it) {
        int j = it * 1024 + tid * 4;
        int d = j >> 6, p = j & 63;
        *(float4*)&Xs[d * 64 + p] = *(const float4*)&xb[d * 1024 + p];
    }
    // ||e||^2 in-block (bit-identical chain to the former init kernel)
    nes[tid]       = code_norm(emb, tid);
    nes[tid + 256] = code_norm(emb, tid + 256);
    __syncthreads();

    // nx per position — R9-verbatim chains (bits shift fl(nx+ne) boundaries)
    {
        int p = tid & 63, g = tid >> 6;
        float s = 0.f;
#pragma unroll
        for (int j = 0; j < 16; ++j) {
            float v = Xs[(g * 16 + j) * 64 + p];
            s = fmaf(v, v, s);
        }
        xpart[g * 64 + p] = s;
    }
    __syncthreads();
    if (tid < 64) {
        xn[tid] = ((xpart[tid] + xpart[64 + tid]) + xpart[128 + tid]) + xpart[192 + tid];
    }

    const int ry = tid >> 5;
    const int cx = tid & 31;

    float best[8];
    int   bidx[8];
#pragma unroll
    for (int i = 0; i < 8; ++i) { best[i] = CUDART_INF_F; bidx[i] = 0; }

    for (int ch = 0; ch < 4; ++ch) {
        __syncthreads();
        // Load E chunk (128 codes x 64 d), scalar stores (R5 pattern)
#pragma unroll
        for (int it = 0; it < 8; ++it) {
            int j  = it * 1024 + tid * 4;
            int cc = j >> 6, d = j & 63;
            float4 e4 = *(const float4*)&emb[(ch * 128 + cc) * DIM + d];
            float* row = &Es[cc * 65 + d];
            row[0] = e4.x; row[1] = e4.y; row[2] = e4.z; row[3] = e4.w;
        }
        __syncthreads();

        // acc[g][j]: code group g (k = ch*128+cx+32g), position pair j
        ull acc[4][4];
#pragma unroll
        for (int g = 0; g < 4; ++g)
#pragma unroll
            for (int j = 0; j < 4; ++j) acc[g][j] = 0ull;

#pragma unroll 16
        for (int d = 0; d < 64; ++d) {
            // scalar e loads: bank = (cx + d) % 32 -> conflict-free
            ull e0 = dup2(Es[(cx      ) * 65 + d]);
            ull e1 = dup2(Es[(cx + 32 ) * 65 + d]);
            ull e2 = dup2(Es[(cx + 64 ) * 65 + d]);
            ull e3 = dup2(Es[(cx + 96 ) * 65 + d]);
            // broadcast 128-bit shared loads: 4 packed position-pairs
            const ulonglong2 a0 = *(const ulonglong2*)&Xs[d * 64 + ry * 8];
            const ulonglong2 a1 = *(const ulonglong2*)&Xs[d * 64 + ry * 8 + 4];
            ffma2(acc[0][0], a0.x, e0); ffma2(acc[0][1], a0.y, e0);
            ffma2(acc[0][2], a1.x, e0); ffma2(acc[0][3], a1.y, e0);
            ffma2(acc[1][0], a0.x, e1); ffma2(acc[1][1], a0.y, e1);
            ffma2(acc[1][2], a1.x, e1); ffma2(acc[1][3], a1.y, e1);
            ffma2(acc[2][0], a0.x, e2); ffma2(acc[2][1], a0.y, e2);
            ffma2(acc[2][2], a1.x, e2); ffma2(acc[2][3], a1.y, e2);
            ffma2(acc[3][0], a0.x, e3); ffma2(acc[3][1], a0.y, e3);
            ffma2(acc[3][2], a1.x, e3); ffma2(acc[3][3], a1.y, e3);
        }

        // Epilogue: emulate jax rounding, running first-index argmin.
        // g ascending => code index ascending within thread.
#pragma unroll
        for (int g = 0; g < 4; ++g) {
            const int k = ch * 128 + cx + g * 32;
            const float ne = nes[k];
#pragma unroll
            for (int j = 0; j < 4; ++j) {
                float sa, sb;
                unpack2(acc[g][j], sa, sb);
                float nxa = xn[ry * 8 + 2 * j];
                float nxb = xn[ry * 8 + 2 * j + 1];
                float da = __fsub_rn(__fadd_rn(nxa, ne), __fmul_rn(2.0f, sa));
                float db = __fsub_rn(__fadd_rn(nxb, ne), __fmul_rn(2.0f, sb));
                if (da < best[2 * j])     { best[2 * j]     = da; bidx[2 * j]     = k; }
                if (db < best[2 * j + 1]) { best[2 * j + 1] = db; bidx[2 * j + 1] = k; }
            }
        }
    }

    // Warp butterfly argmin per position (tie -> smaller index)
#pragma unroll
    for (int i = 0; i < 8; ++i) {
        float v = best[i];
        int   id = bidx[i];
#pragma unroll
        for (int off = 16; off > 0; off >>= 1) {
            float ov = __shfl_xor_sync(0xffffffffu, v, off);
            int   oi = __shfl_xor_sync(0xffffffffu, id, off);
            if (ov < v || (ov == v && oi < id)) { v = ov; id = oi; }
        }
        if (cx == 0) {
            widx[ry * 8 + i] = id;
            atomicAdd(&g_hist[id], 1);
        }
    }
    __syncthreads();

    // ---------------- fused output (Es reused as qs[64][65]) ----------------
    float* out_nchw = out + 1;
    float* out_flat = out + 2 + NCHW_ELEMS;

    // Pass 1 (pos-major): coalesced codebook gather into qs
#pragma unroll
    for (int it = 0; it < 16; ++it) {
        int j = it * 256 + tid;
        int p = j >> 6, d = j & 63;
        Es[p * 65 + d] = emb[widx[p] * DIM + d];
    }
    __syncthreads();

    // Pass 2 (d-major): x from resident Xs, NCHW q_st write, loss accumulation
    float lsum = 0.f;
#pragma unroll
    for (int it = 0; it < 16; ++it) {
        int j = it * 256 + tid;
        int d = j >> 6, p = j & 63;
        size_t g = (size_t)b * 65536 + (size_t)d * 1024 + hw + p;
        float q  = Es[p * 65 + d];          // stride 65 -> conflict-free
        float xv = Xs[d * 64 + p];
        float df  = __fsub_rn(q, xv);       // fl32(q - x)
        float qst = __fadd_rn(xv, df);      // fl32(x + (q - x))
        out_nchw[g] = qst;
        Es[p * 65 + d] = qst;
        lsum = fmaf(df, df, lsum);
    }
    __syncthreads();

    // Pass 3 (pos-major): flat NHWC q_st write (coalesced)
#pragma unroll
    for (int it = 0; it < 16; ++it) {
        int j = it * 256 + tid;
        int p = j >> 6, d = j & 63;
        out_flat[(size_t)(posBase + p) * DIM + d] = Es[p * 65 + d];
    }

    // Loss partial; reuse xpart as red[256]
    float* red = xpart;
    red[tid] = lsum;
    __syncthreads();
    for (int s = 128; s > 0; s >>= 1) {
        if (tid < s) red[tid] += red[tid + s];
        __syncthreads();
    }
    if (tid == 0) g_partial[blockIdx.x] = red[0];

    // ---------------- last-block finalize (threadFenceReduction) ------------
    __threadfence();
    __syncthreads();
    if (tid == 0) {
        int c = atomicAdd(&g_hist[KCB], 1);
        isLast = (c == GRID - 1);
    }
    __syncthreads();
    if (!isLast) return;

    __threadfence();
    // Loss: 1024 partials -> 256 -> tree (grouping change only affects out[0]
    // at ~1e-8 rel; tolerance is 1e-3)
    red[tid] = (__ldcg(&g_partial[tid])       + __ldcg(&g_partial[tid + 256]))
             + (__ldcg(&g_partial[tid + 512]) + __ldcg(&g_partial[tid + 768]));
    __syncthreads();
    for (int s = 128; s > 0; s >>= 1) {
        if (tid < s) red[tid] += red[tid + s];
        __syncthreads();
    }
    if (tid == 0) {
        out[0] = 1.25f * (red[0] / (float)NCHW_ELEMS);
    }
    __syncthreads();

    // Perplexity (R8-validated tail: two codes per thread, then tree)
    float p0 = (float)__ldcg(&g_hist[tid])       * (1.0f / 65536.0f);
    float p1 = (float)__ldcg(&g_hist[tid + 256]) * (1.0f / 65536.0f);
    red[tid] = p0 * logf(p0 + 1e-10f) + p1 * logf(p1 + 1e-10f);
    __syncthreads();
    for (int s = 128; s > 0; s >>= 1) {
        if (tid < s) red[tid] += red[tid + s];
        __syncthreads();
    }
    if (tid == 0) {
        out[NCHW_ELEMS + 1] = expf(-red[0]);
    }
}

// ---------------------------------------------------------------------------
extern "C" void kernel_launch(void* const* d_in, const int* in_sizes, int n_in,
                              void* d_out, int out_size) {
    const float* x   = (const float*)d_in[0];   // [64,64,32,32] f32 NCHW
    const float* emb = (const float*)d_in[1];   // [512,64] f32
    float* out = (float*)d_out;

    // Zero histogram + completion counter (graph memset node; no allocation)
    void* hp = nullptr;
    cudaGetSymbolAddress(&hp, g_hist);
    cudaMemsetAsync(hp, 0, (KCB + 1) * sizeof(int));

    vq_fused_kernel<<<GRID, 256>>>(x, emb, out);
}

// round 14
// speedup vs baseline: 3.7549x; 1.0161x over previous
#include <cuda_runtime.h>
#include <math_constants.h>

// Problem constants
#define NPOS 65536   // 64 * 32 * 32 positions
#define DIM  64      // embedding dim
#define KCB  512     // codebook size
#define NCHW_ELEMS 4194304  // 64*64*32*32
#define GRID 1024

typedef unsigned long long ull;

// Scratch (allocation-free: __device__ globals)
// g_hist[0..511] zeroed each replay by the memset node in kernel_launch.
__device__ int   g_hist[KCB];
__device__ float g_partial[GRID];

// Packed fp32x2 FMA (Blackwell): per-lane IEEE identical to scalar fmaf.
__device__ __forceinline__ void ffma2(ull& acc, ull a, ull b) {
    asm("fma.rn.f32x2 %0, %1, %2, %0;" : "+l"(acc) : "l"(a), "l"(b));
}
__device__ __forceinline__ ull dup2(float v) {
    ull r;
    asm("mov.b64 %0, {%1, %1};" : "=l"(r) : "f"(v));
    return r;
}
__device__ __forceinline__ void unpack2(ull p, float& lo, float& hi) {
    asm("mov.b64 {%0, %1}, %2;" : "=f"(lo), "=f"(hi) : "l"(p));
}

// ||e_k||^2 — exact chain (bitwise identical to the former init kernel).
// All registers here are dead before the GEMM mainloop starts.
__device__ __forceinline__ float code_norm(const float* __restrict__ emb, int k) {
    const float4* e4 = (const float4*)(emb + k * DIM);
    float s = 0.f;
#pragma unroll
    for (int j = 0; j < 16; ++j) {
        float4 v = e4[j];
        s = fmaf(v.x, v.x, s);
        s = fmaf(v.y, v.y, s);
        s = fmaf(v.z, v.z, s);
        s = fmaf(v.w, v.w, s);
    }
    return s;
}

// ---------------------------------------------------------------------------
// Fused kernel (R9 GEMM core verbatim): FFMA2 argmin GEMM + fused outputs +
// loss partial. In-block ne computation replaces the init kernel; the
// logf-heavy finalize stays in its own kernel (register budget!).
// dist = fl32(fl32(nx+ne) - fl32(2*s)), first-index argmin (jax emulation).
// Grid: 1024 blocks x 256 threads. Block = 64 positions x 512 codes,
// 4 chunks of 128 codes. Warp ry: positions ry*8..ry*8+7 (f32x2 pairs).
// Lane cx: codes ch*128 + cx + {0,32,64,96}.
// ---------------------------------------------------------------------------
__global__ __launch_bounds__(256, 2) void vq_fused_kernel(
    const float* __restrict__ x, const float* __restrict__ emb,
    float* __restrict__ out)
{
    __shared__ float Xs[64 * 64];      // [d][pos], d-major (pos pairs adjacent)
    __shared__ float Es[128 * 65];     // [code][d] pad 65; reused as qs[64][65]
    __shared__ float nes[KCB];         // ||e_k||^2 (computed in-block, L2-hot)
    __shared__ float xpart[4 * 64];    // nx partials; reused as loss red[256]
    __shared__ float xn[64];           // ||x_p||^2 (binade-correct suffices)
    __shared__ int   widx[64];         // winning code per position

    const int tid = threadIdx.x;
    const int posBase = blockIdx.x * 64;
    const int b  = posBase >> 10;       // 1024 positions per batch image
    const int hw = posBase & 1023;
    const float* xb = x + (size_t)b * 65536 + hw;  // + d*1024 + p

    // Load X tile (float4, coalesced): Xs[d*64+p]
#pragma unroll
    for (int it = 0; it < 4; ++it) {
        int j = it * 1024 + tid * 4;
        int d = j >> 6, p = j & 63;
        *(float4*)&Xs[d * 64 + p] = *(const float4*)&xb[d * 1024 + p];
    }
    // ||e||^2 in-block (bit-identical chain; registers dead before mainloop)
    nes[tid]       = code_norm(emb, tid);
    nes[tid + 256] = code_norm(emb, tid + 256);
    __syncthreads();

    // nx per position — R9-verbatim chains (bits shift fl(nx+ne) boundaries)
    {
        int p = tid & 63, g = tid >> 6;
        float s = 0.f;
#pragma unroll
        for (int j = 0; j < 16; ++j) {
            float v = Xs[(g * 16 + j) * 64 + p];
            s = fmaf(v, v, s);
        }
        xpart[g * 64 + p] = s;
    }
    __syncthreads();
    if (tid < 64) {
        xn[tid] = ((xpart[tid] + xpart[64 + tid]) + xpart[128 + tid]) + xpart[192 + tid];
    }

    const int ry = tid >> 5;
    const int cx = tid & 31;

    float best[8];
    int   bidx[8];
#pragma unroll
    for (int i = 0; i < 8; ++i) { best[i] = CUDART_INF_F; bidx[i] = 0; }

    for (int ch = 0; ch < 4; ++ch) {
        __syncthreads();
        // Load E chunk (128 codes x 64 d), scalar stores (R5 pattern)
#pragma unroll
        for (int it = 0; it < 8; ++it) {
            int j  = it * 1024 + tid * 4;
            int cc = j >> 6, d = j & 63;
            float4 e4 = *(const float4*)&emb[(ch * 128 + cc) * DIM + d];
            float* row = &Es[cc * 65 + d];
            row[0] = e4.x; row[1] = e4.y; row[2] = e4.z; row[3] = e4.w;
        }
        __syncthreads();

        // acc[g][j]: code group g (k = ch*128+cx+32g), position pair j
        ull acc[4][4];
#pragma unroll
        for (int g = 0; g < 4; ++g)
#pragma unroll
            for (int j = 0; j < 4; ++j) acc[g][j] = 0ull;

#pragma unroll 16
        for (int d = 0; d < 64; ++d) {
            // scalar e loads: bank = (cx + d) % 32 -> conflict-free
            ull e0 = dup2(Es[(cx      ) * 65 + d]);
            ull e1 = dup2(Es[(cx + 32 ) * 65 + d]);
            ull e2 = dup2(Es[(cx + 64 ) * 65 + d]);
            ull e3 = dup2(Es[(cx + 96 ) * 65 + d]);
            // broadcast 128-bit shared loads: 4 packed position-pairs
            const ulonglong2 a0 = *(const ulonglong2*)&Xs[d * 64 + ry * 8];
            const ulonglong2 a1 = *(const ulonglong2*)&Xs[d * 64 + ry * 8 + 4];
            ffma2(acc[0][0], a0.x, e0); ffma2(acc[0][1], a0.y, e0);
            ffma2(acc[0][2], a1.x, e0); ffma2(acc[0][3], a1.y, e0);
            ffma2(acc[1][0], a0.x, e1); ffma2(acc[1][1], a0.y, e1);
            ffma2(acc[1][2], a1.x, e1); ffma2(acc[1][3], a1.y, e1);
            ffma2(acc[2][0], a0.x, e2); ffma2(acc[2][1], a0.y, e2);
            ffma2(acc[2][2], a1.x, e2); ffma2(acc[2][3], a1.y, e2);
            ffma2(acc[3][0], a0.x, e3); ffma2(acc[3][1], a0.y, e3);
            ffma2(acc[3][2], a1.x, e3); ffma2(acc[3][3], a1.y, e3);
        }

        // Epilogue: emulate jax rounding, running first-index argmin.
        // g ascending => code index ascending within thread.
#pragma unroll
        for (int g = 0; g < 4; ++g) {
            const int k = ch * 128 + cx + g * 32;
            const float ne = nes[k];
#pragma unroll
            for (int j = 0; j < 4; ++j) {
                float sa, sb;
                unpack2(acc[g][j], sa, sb);
                float nxa = xn[ry * 8 + 2 * j];
                float nxb = xn[ry * 8 + 2 * j + 1];
                float da = __fsub_rn(__fadd_rn(nxa, ne), __fmul_rn(2.0f, sa));
                float db = __fsub_rn(__fadd_rn(nxb, ne), __fmul_rn(2.0f, sb));
                if (da < best[2 * j])     { best[2 * j]     = da; bidx[2 * j]     = k; }
                if (db < best[2 * j + 1]) { best[2 * j + 1] = db; bidx[2 * j + 1] = k; }
            }
        }
    }

    // Warp butterfly argmin per position (tie -> smaller index)
#pragma unroll
    for (int i = 0; i < 8; ++i) {
        float v = best[i];
        int   id = bidx[i];
#pragma unroll
        for (int off = 16; off > 0; off >>= 1) {
            float ov = __shfl_xor_sync(0xffffffffu, v, off);
            int   oi = __shfl_xor_sync(0xffffffffu, id, off);
            if (ov < v || (ov == v && oi < id)) { v = ov; id = oi; }
        }
        if (cx == 0) {
            widx[ry * 8 + i] = id;
            atomicAdd(&g_hist[id], 1);
        }
    }
    __syncthreads();

    // ---------------- fused output (Es reused as qs[64][65]) ----------------
    float* out_nchw = out + 1;
    float* out_flat = out + 2 + NCHW_ELEMS;

    // Pass 1 (pos-major): coalesced codebook gather into qs
#pragma unroll
    for (int it = 0; it < 16; ++it) {
        int j = it * 256 + tid;
        int p = j >> 6, d = j & 63;
        Es[p * 65 + d] = emb[widx[p] * DIM + d];
    }
    __syncthreads();

    // Pass 2 (d-major): x from resident Xs, NCHW q_st write, loss accumulation
    float lsum = 0.f;
#pragma unroll
    for (int it = 0; it < 16; ++it) {
        int j = it * 256 + tid;
        int d = j >> 6, p = j & 63;
        size_t g = (size_t)b * 65536 + (size_t)d * 1024 + hw + p;
        float q  = Es[p * 65 + d];          // stride 65 -> conflict-free
        float xv = Xs[d * 64 + p];
        float df  = __fsub_rn(q, xv);       // fl32(q - x)
        float qst = __fadd_rn(xv, df);      // fl32(x + (q - x))
        out_nchw[g] = qst;
        Es[p * 65 + d] = qst;
        lsum = fmaf(df, df, lsum);
    }
    __syncthreads();

    // Pass 3 (pos-major): flat NHWC q_st write (coalesced)
#pragma unroll
    for (int it = 0; it < 16; ++it) {
        int j = it * 256 + tid;
        int p = j >> 6, d = j & 63;
        out_flat[(size_t)(posBase + p) * DIM + d] = Es[p * 65 + d];
    }

    // Loss partial; reuse xpart as red[256]
    float* red = xpart;
    red[tid] = lsum;
    __syncthreads();
    for (int s = 128; s > 0; s >>= 1) {
        if (tid < s) red[tid] += red[tid + s];
        __syncthreads();
    }
    if (tid == 0) g_partial[blockIdx.x] = red[0];
}

// ---------------------------------------------------------------------------
// Finalize: loss scalar + perplexity (fp32, deterministic). Keeps logf OUT
// of the hot kernel's register budget.
// ---------------------------------------------------------------------------
__global__ void vq_finalize_kernel(float* __restrict__ out) {
    __shared__ float red[512];
    const int t = threadIdx.x;

    red[t] = g_partial[t] + g_partial[t + 512];   // 1024 partials -> 512
    __syncthreads();
    for (int s = 256; s > 0; s >>= 1) {
        if (t < s) red[t] += red[t + s];
        __syncthreads();
    }
    if (t == 0) {
        out[0] = 1.25f * (red[0] / (float)NCHW_ELEMS);
    }
    __syncthreads();

    float p = (float)g_hist[t] * (1.0f / 65536.0f);
    red[t] = p * logf(p + 1e-10f);
    __syncthreads();
    for (int s = 256; s > 0; s >>= 1) {
        if (t < s) red[t] += red[t + s];
        __syncthreads();
    }
    if (t == 0) {
        out[NCHW_ELEMS + 1] = expf(-red[0]);
    }
}

// ---------------------------------------------------------------------------
extern "C" void kernel_launch(void* const* d_in, const int* in_sizes, int n_in,
                              void* d_out, int out_size) {
    const float* x   = (const float*)d_in[0];   // [64,64,32,32] f32 NCHW
    const float* emb = (const float*)d_in[1];   // [512,64] f32
    float* out = (float*)d_out;

    // Zero histogram (graph memset node; no allocation)
    void* hp = nullptr;
    cudaGetSymbolAddress(&hp, g_hist);
    cudaMemsetAsync(hp, 0, KCB * sizeof(int));

    vq_fused_kernel<<<GRID, 256>>>(x, emb, out);
    vq_finalize_kernel<<<1, 512>>>(out);
}

// round 15
// speedup vs baseline: 4.4816x; 1.1935x over previous
#include <cuda_runtime.h>
#include <math_constants.h>

// Problem constants
#define NPOS 65536   // 64 * 32 * 32 positions
#define DIM  64      // embedding dim
#define KCB  512     // codebook size
#define NCHW_ELEMS 4194304  // 64*64*32*32
#define GRID 1024

typedef unsigned long long ull;

// Scratch (allocation-free: __device__ globals)
// g_hist zeroed each replay by the memset node in kernel_launch.
__device__ int   g_hist[KCB];
__device__ float g_ne[KCB];          // ||e_k||^2 in fp32
__device__ float g_partial[GRID];

// Packed fp32x2 FMA (Blackwell): per-lane IEEE identical to scalar fmaf.
__device__ __forceinline__ void ffma2(ull& acc, ull a, ull b) {
    asm("fma.rn.f32x2 %0, %1, %2, %0;" : "+l"(acc) : "l"(a), "l"(b));
}
__device__ __forceinline__ ull dup2(float v) {
    ull r;
    asm("mov.b64 %0, {%1, %1};" : "=l"(r) : "f"(v));
    return r;
}
__device__ __forceinline__ void unpack2(ull p, float& lo, float& hi) {
    asm("mov.b64 {%0, %1}, %2;" : "=f"(lo), "=f"(hi) : "l"(p));
}

// ---------------------------------------------------------------------------
// Init: ||e_k||^2 only (hist is zeroed by the memset node). Spread across
// 16 SMs (grid 16 x 32, one code per thread) so the 16 float4-LDG chains
// are latency-parallel instead of serialized on one SM.
// Per-code fmaf chain is BIT-IDENTICAL to all prior rounds.
// ---------------------------------------------------------------------------
__global__ void vq_init_kernel(const float* __restrict__ emb) {
    int t = blockIdx.x * 32 + threadIdx.x;   // 0..511
    const float4* e4 = (const float4*)(emb + t * DIM);
    float s = 0.f;
#pragma unroll
    for (int j = 0; j < 16; ++j) {
        float4 v = e4[j];
        s = fmaf(v.x, v.x, s);
        s = fmaf(v.y, v.y, s);
        s = fmaf(v.z, v.z, s);
        s = fmaf(v.w, v.w, s);
    }
    g_ne[t] = s;
}

// ---------------------------------------------------------------------------
// Fused kernel — VERBATIM R9 (117.2 µs champion): FFMA2 argmin GEMM + fused
// outputs + loss partial. NOTHING may be added here (register cap).
// dist = fl32(fl32(nx+ne) - fl32(2*s)), first-index argmin (jax emulation).
// Grid: 1024 blocks x 256 threads. Block = 64 positions x 512 codes,
// 4 chunks of 128 codes. Warp ry: positions ry*8..ry*8+7 (f32x2 pairs).
// Lane cx: codes ch*128 + cx + {0,32,64,96}.
// ---------------------------------------------------------------------------
__global__ __launch_bounds__(256, 2) void vq_fused_kernel(
    const float* __restrict__ x, const float* __restrict__ emb,
    float* __restrict__ out)
{
    __shared__ float Xs[64 * 64];      // [d][pos], d-major (pos pairs adjacent)
    __shared__ float Es[128 * 65];     // [code][d] pad 65; reused as qs[64][65]
    __shared__ float nes[KCB];         // ||e_k||^2 staged
    __shared__ float xpart[4 * 64];    // nx partials; reused as loss red[256]
    __shared__ float xn[64];           // ||x_p||^2 (binade-correct suffices)
    __shared__ int   widx[64];         // winning code per position

    const int tid = threadIdx.x;
    const int posBase = blockIdx.x * 64;
    const int b  = posBase >> 10;       // 1024 positions per batch image
    const int hw = posBase & 1023;
    const float* xb = x + (size_t)b * 65536 + hw;  // + d*1024 + p

    // Load X tile (float4, coalesced): Xs[d*64+p]
#pragma unroll
    for (int it = 0; it < 4; ++it) {
        int j = it * 1024 + tid * 4;
        int d = j >> 6, p = j & 63;
        *(float4*)&Xs[d * 64 + p] = *(const float4*)&xb[d * 1024 + p];
    }
    // Stage ne
    nes[tid] = g_ne[tid];
    nes[tid + 256] = g_ne[tid + 256];
    __syncthreads();

    // nx per position — R9-verbatim chains (bits shift fl(nx+ne) boundaries)
    {
        int p = tid & 63, g = tid >> 6;
        float s = 0.f;
#pragma unroll
        for (int j = 0; j < 16; ++j) {
            float v = Xs[(g * 16 + j) * 64 + p];
            s = fmaf(v, v, s);
        }
        xpart[g * 64 + p] = s;
    }
    __syncthreads();
    if (tid < 64) {
        xn[tid] = ((xpart[tid] + xpart[64 + tid]) + xpart[128 + tid]) + xpart[192 + tid];
    }

    const int ry = tid >> 5;
    const int cx = tid & 31;

    float best[8];
    int   bidx[8];
#pragma unroll
    for (int i = 0; i < 8; ++i) { best[i] = CUDART_INF_F; bidx[i] = 0; }

    for (int ch = 0; ch < 4; ++ch) {
        __syncthreads();
        // Load E chunk (128 codes x 64 d), scalar stores (R5 pattern)
#pragma unroll
        for (int it = 0; it < 8; ++it) {
            int j  = it * 1024 + tid * 4;
            int cc = j >> 6, d = j & 63;
            float4 e4 = *(const float4*)&emb[(ch * 128 + cc) * DIM + d];
            float* row = &Es[cc * 65 + d];
            row[0] = e4.x; row[1] = e4.y; row[2] = e4.z; row[3] = e4.w;
        }
        __syncthreads();

        // acc[g][j]: code group g (k = ch*128+cx+32g), position pair j
        ull acc[4][4];
#pragma unroll
        for (int g = 0; g < 4; ++g)
#pragma unroll
            for (int j = 0; j < 4; ++j) acc[g][j] = 0ull;

#pragma unroll 16
        for (int d = 0; d < 64; ++d) {
            // scalar e loads: bank = (cx + d) % 32 -> conflict-free
            ull e0 = dup2(Es[(cx      ) * 65 + d]);
            ull e1 = dup2(Es[(cx + 32 ) * 65 + d]);
            ull e2 = dup2(Es[(cx + 64 ) * 65 + d]);
            ull e3 = dup2(Es[(cx + 96 ) * 65 + d]);
            // broadcast 128-bit shared loads: 4 packed position-pairs
            const ulonglong2 a0 = *(const ulonglong2*)&Xs[d * 64 + ry * 8];
            const ulonglong2 a1 = *(const ulonglong2*)&Xs[d * 64 + ry * 8 + 4];
            ffma2(acc[0][0], a0.x, e0); ffma2(acc[0][1], a0.y, e0);
            ffma2(acc[0][2], a1.x, e0); ffma2(acc[0][3], a1.y, e0);
            ffma2(acc[1][0], a0.x, e1); ffma2(acc[1][1], a0.y, e1);
            ffma2(acc[1][2], a1.x, e1); ffma2(acc[1][3], a1.y, e1);
            ffma2(acc[2][0], a0.x, e2); ffma2(acc[2][1], a0.y, e2);
            ffma2(acc[2][2], a1.x, e2); ffma2(acc[2][3], a1.y, e2);
            ffma2(acc[3][0], a0.x, e3); ffma2(acc[3][1], a0.y, e3);
            ffma2(acc[3][2], a1.x, e3); ffma2(acc[3][3], a1.y, e3);
        }

        // Epilogue: emulate jax rounding, running first-index argmin.
        // g ascending => code index ascending within thread.
#pragma unroll
        for (int g = 0; g < 4; ++g) {
            const int k = ch * 128 + cx + g * 32;
            const float ne = nes[k];
#pragma unroll
            for (int j = 0; j < 4; ++j) {
                float sa, sb;
                unpack2(acc[g][j], sa, sb);
                float nxa = xn[ry * 8 + 2 * j];
                float nxb = xn[ry * 8 + 2 * j + 1];
                float da = __fsub_rn(__fadd_rn(nxa, ne), __fmul_rn(2.0f, sa));
                float db = __fsub_rn(__fadd_rn(nxb, ne), __fmul_rn(2.0f, sb));
                if (da < best[2 * j])     { best[2 * j]     = da; bidx[2 * j]     = k; }
                if (db < best[2 * j + 1]) { best[2 * j + 1] = db; bidx[2 * j + 1] = k; }
            }
        }
    }

    // Warp butterfly argmin per position (tie -> smaller index)
#pragma unroll
    for (int i = 0; i < 8; ++i) {
        float v = best[i];
        int   id = bidx[i];
#pragma unroll
        for (int off = 16; off > 0; off >>= 1) {
            float ov = __shfl_xor_sync(0xffffffffu, v, off);
            int   oi = __shfl_xor_sync(0xffffffffu, id, off);
            if (ov < v || (ov == v && oi < id)) { v = ov; id = oi; }
        }
        if (cx == 0) {
            widx[ry * 8 + i] = id;
            atomicAdd(&g_hist[id], 1);
        }
    }
    __syncthreads();

    // ---------------- fused output (Es reused as qs[64][65]) ----------------
    float* out_nchw = out + 1;
    float* out_flat = out + 2 + NCHW_ELEMS;

    // Pass 1 (pos-major): coalesced codebook gather into qs
#pragma unroll
    for (int it = 0; it < 16; ++it) {
        int j = it * 256 + tid;
        int p = j >> 6, d = j & 63;
        Es[p * 65 + d] = emb[widx[p] * DIM + d];
    }
    __syncthreads();

    // Pass 2 (d-major): x from resident Xs, NCHW q_st write, loss accumulation
    float lsum = 0.f;
#pragma unroll
    for (int it = 0; it < 16; ++it) {
        int j = it * 256 + tid;
        int d = j >> 6, p = j & 63;
        size_t g = (size_t)b * 65536 + (size_t)d * 1024 + hw + p;
        float q  = Es[p * 65 + d];          // stride 65 -> conflict-free
        float xv = Xs[d * 64 + p];
        float df  = __fsub_rn(q, xv);       // fl32(q - x)
        float qst = __fadd_rn(xv, df);      // fl32(x + (q - x))
        out_nchw[g] = qst;
        Es[p * 65 + d] = qst;
        lsum = fmaf(df, df, lsum);
    }
    __syncthreads();

    // Pass 3 (pos-major): flat NHWC q_st write (coalesced)
#pragma unroll
    for (int it = 0; it < 16; ++it) {
        int j = it * 256 + tid;
        int p = j >> 6, d = j & 63;
        out_flat[(size_t)(posBase + p) * DIM + d] = Es[p * 65 + d];
    }

    // Loss partial; reuse xpart as red[256]
    float* red = xpart;
    red[tid] = lsum;
    __syncthreads();
    for (int s = 128; s > 0; s >>= 1) {
        if (tid < s) red[tid] += red[tid + s];
        __syncthreads();
    }
    if (tid == 0) g_partial[blockIdx.x] = red[0];
}

// ---------------------------------------------------------------------------
// Finalize: loss scalar + perplexity (fp32, deterministic). Keeps logf OUT
// of the hot kernel's register budget.
// ---------------------------------------------------------------------------
__global__ void vq_finalize_kernel(float* __restrict__ out) {
    __shared__ float red[512];
    const int t = threadIdx.x;

    red[t] = g_partial[t] + g_partial[t + 512];   // 1024 partials -> 512
    __syncthreads();
    for (int s = 256; s > 0; s >>= 1) {
        if (t < s) red[t] += red[t + s];
        __syncthreads();
    }
    if (t == 0) {
        out[0] = 1.25f * (red[0] / (float)NCHW_ELEMS);
    }
    __syncthreads();

    float p = (float)g_hist[t] * (1.0f / 65536.0f);
    red[t] = p * logf(p + 1e-10f);
    __syncthreads();
    for (int s = 256; s > 0; s >>= 1) {
        if (t < s) red[t] += red[t + s];
        __syncthreads();
    }
    if (t == 0) {
        out[NCHW_ELEMS + 1] = expf(-red[0]);
    }
}

// ---------------------------------------------------------------------------
extern "C" void kernel_launch(void* const* d_in, const int* in_sizes, int n_in,
                              void* d_out, int out_size) {
    const float* x   = (const float*)d_in[0];   // [64,64,32,32] f32 NCHW
    const float* emb = (const float*)d_in[1];   // [512,64] f32
    float* out = (float*)d_out;

    // Zero histogram (graph memset node; no allocation)
    void* hp = nullptr;
    cudaGetSymbolAddress(&hp, g_hist);
    cudaMemsetAsync(hp, 0, KCB * sizeof(int));

    vq_init_kernel<<<16, 32>>>(emb);
    vq_fused_kernel<<<GRID, 256>>>(x, emb, out);
    vq_finalize_kernel<<<1, 512>>>(out);
}